// round 9
// baseline (speedup 1.0000x reference)
#include <cuda_runtime.h>
#include <stdint.h>

// Unpack padded [B, Lmax, H, D] fp32 -> packed [N, H, D], N = sum(lengths).
// Row = H*D = 2048 floats = 512 float4 = 8 KB.
//
// v4: cp.async (LDGSTS) smem pipeline. MLP comes from async-copy depth, not
// registers, so occupancy/register pressure no longer caps in-flight loads.
//   - chunk = 4 rows = 32 KB; 3 stages = 96 KB dynamic smem; 2 blocks/SM.
//   - persistent strided chunk loop kills wave-tail quantization.
//   - stores: LDS.128 + STG.128 streaming (.cs).
//
// lengths dtype detected on-device (JAX x64-off downcasts int64 -> int32):
// parse as contiguous int32 AND int64-low-words; whichever sums to N wins.

#define ROW_VEC4    512
#define THREADS     256
#define CHUNK_ROWS  4
#define STAGES      3
#define CHUNK_VEC4  (CHUNK_ROWS * ROW_VEC4)          // 2048 float4
#define SMEM_BYTES  (STAGES * CHUNK_VEC4 * 16)       // 98304
#define MAX_B       32

__device__ __forceinline__ void cp_async16(uint32_t smem_addr, const float4* gptr) {
    asm volatile("cp.async.cg.shared.global [%0], [%1], 16;\n"
                 :: "r"(smem_addr), "l"(gptr));
}
__device__ __forceinline__ void cp_commit() {
    asm volatile("cp.async.commit_group;\n" ::: "memory");
}
__device__ __forceinline__ void cp_wait() {
    asm volatile("cp.async.wait_group %0;\n" :: "n"(STAGES - 1) : "memory");
}

__global__ void __launch_bounds__(THREADS) unpack_pipe_kernel(
    const float4* __restrict__ in,        // [B, Lmax, 512]
    const int* __restrict__ lengths_raw,  // [B] raw words
    float4* __restrict__ out,             // [N, 512]
    int B, int Lmax, int N, int numChunks)
{
    extern __shared__ float4 smem[];      // [STAGES][CHUNK_VEC4]
    const int tx = threadIdx.x;

    // --- dtype detection (B tiny; L1-resident, uniform across threads) ---
    long long sum32 = 0, sum64 = 0;
    #pragma unroll 8
    for (int i = 0; i < B; ++i) {
        sum32 += __ldg(&lengths_raw[i]);
        sum64 += __ldg(&lengths_raw[2 * i]);
    }
    const bool is64 = (sum64 == (long long)N) && (sum32 != (long long)N);

    // cumulative starts (register array, uniform)
    int len[MAX_B > 8 ? MAX_B : 8];
    #pragma unroll 8
    for (int i = 0; i < B; ++i)
        len[i] = is64 ? __ldg(&lengths_raw[2 * i]) : __ldg(&lengths_raw[i]);

    // resolve source float4-offset of output row n (or -1 if n >= N)
    auto resolve = [&](int n) -> int {
        if (n >= N) return -1;
        int s = 0, b = 0, t = 0;
        #pragma unroll 8
        for (int i = 0; i < B; ++i) {
            if (n >= s && n < s + len[i]) { b = i; t = n - s; }
            s += len[i];
        }
        return (b * Lmax + t) * ROW_VEC4;   // fits in int (< 16.8M)
    };

    const uint32_t smem_base =
        (uint32_t)__cvta_generic_to_shared(smem);

    // issue cp.asyncs for my i-th chunk into stage buffer; commit always.
    auto issue_chunk = [&](int i) {
        long long c = (long long)blockIdx.x + (long long)i * gridDim.x;
        if (c < numChunks) {
            const int n0 = (int)c * CHUNK_ROWS;
            uint32_t buf = smem_base + (uint32_t)(i % STAGES) * (CHUNK_VEC4 * 16);
            #pragma unroll
            for (int r = 0; r < CHUNK_ROWS; ++r) {
                const int off = resolve(n0 + r);
                if (off >= 0) {
                    #pragma unroll
                    for (int j = 0; j < 2; ++j) {
                        const int e = tx + j * THREADS;
                        cp_async16(buf + (uint32_t)(r * ROW_VEC4 + e) * 16,
                                   in + off + e);
                    }
                }
            }
        }
        cp_commit();   // commit even if empty to keep group accounting uniform
    };

    // my chunk count
    int myChunks = 0;
    if ((int)blockIdx.x < numChunks)
        myChunks = (numChunks - blockIdx.x + gridDim.x - 1) / gridDim.x;

    // prologue: fill pipeline
    #pragma unroll
    for (int s = 0; s < STAGES; ++s) issue_chunk(s);

    // steady state
    for (int i = 0; i < myChunks; ++i) {
        cp_wait();                 // chunk i landed
        __syncthreads();

        const int c = blockIdx.x + i * gridDim.x;
        const int n0 = c * CHUNK_ROWS;
        const float4* buf = smem + (i % STAGES) * CHUNK_VEC4;
        #pragma unroll
        for (int r = 0; r < CHUNK_ROWS; ++r) {
            const int n = n0 + r;
            if (n < N) {
                float4* dst = out + (size_t)n * ROW_VEC4;
                #pragma unroll
                for (int j = 0; j < 2; ++j) {
                    const int e = tx + j * THREADS;
                    __stcs(&dst[e], buf[r * ROW_VEC4 + e]);
                }
            }
        }
        __syncthreads();           // all readers done before stage refill
        issue_chunk(i + STAGES);
    }
}

extern "C" void kernel_launch(void* const* d_in, const int* in_sizes, int n_in,
                              void* d_out, int out_size)
{
    const float4* packed = (const float4*)d_in[0];   // [B, Lmax, H, D] fp32
    const int* lengths_raw = (const int*)d_in[1];    // [B] (int32 or int64 words)

    int B = in_sizes[1];
    if (B > MAX_B) B = MAX_B;
    long long total_in = in_sizes[0];                     // B*Lmax*2048 floats
    int Lmax = (int)(total_in / ((long long)B * 2048));   // 4096

    int N = out_size / 2048;                              // packed rows
    int numChunks = (N + CHUNK_ROWS - 1) / CHUNK_ROWS;

    float4* out = (float4*)d_out;

    static int attr_done = 0;   // idempotent attribute set (not an alloc)
    if (!attr_done) {
        cudaFuncSetAttribute(unpack_pipe_kernel,
                             cudaFuncAttributeMaxDynamicSharedMemorySize,
                             SMEM_BYTES);
        attr_done = 1;
    }

    int grid = 2 * 148;                      // 2 blocks/SM (96 KB smem each)
    if (numChunks > 0 && grid > numChunks) grid = numChunks;
    if (grid < 1) grid = 1;

    unpack_pipe_kernel<<<grid, THREADS, SMEM_BYTES>>>(
        packed, lengths_raw, out, B, Lmax, N, numChunks);
}

// round 10
// speedup vs baseline: 1.0656x; 1.0656x over previous
#include <cuda_runtime.h>
#include <stdint.h>

// Unpack padded [B, Lmax, H, D] fp32 -> packed [N, H, D], N = sum(lengths).
// Row = H*D = 2048 floats = 512 float4 = 8 KB.
//
// v5: R7's two-phase register copy (4 rows/chunk, 8 front-batched LDG.128 +
// 8 STG.128 per thread, streaming hints) + WORK-STEALING persistent grid.
// A device-global atomic ticket removes wave-tail quantization (R7 lost ~12%
// to a 4.4-wave grid rounding up to 5). Ticket reset by a tiny first kernel
// so the launch stays graph-capturable and deterministic (each chunk is
// written exactly once; values don't depend on assignment order).
//
// lengths dtype detected on-device (JAX x64-off downcasts int64 -> int32):
// parse as contiguous int32 AND int64-low-words; whichever sums to N wins.

#define ROW_VEC4    512
#define THREADS     256
#define CHUNK_ROWS  4
#define VEC_PER_THREAD 2            // 512/256 per row
#define MAX_B       32

__device__ unsigned int g_ticket;

__global__ void reset_ticket_kernel() { g_ticket = 0u; }

__global__ void __launch_bounds__(THREADS) unpack_ws_kernel(
    const float4* __restrict__ in,        // [B, Lmax, 512]
    const int* __restrict__ lengths_raw,  // [B] raw words
    float4* __restrict__ out,             // [N, 512]
    int B, int Lmax, int N, int numChunks)
{
    __shared__ int s_len[MAX_B];
    __shared__ int s_chunk;
    const int tx = threadIdx.x;

    // --- dtype detection + lengths -> smem (saves registers) ---
    if (tx == 0) {
        long long sum32 = 0, sum64 = 0;
        for (int i = 0; i < B; ++i) {
            sum32 += lengths_raw[i];
            sum64 += lengths_raw[2 * i];
        }
        const bool is64 = (sum64 == (long long)N) && (sum32 != (long long)N);
        for (int i = 0; i < B; ++i)
            s_len[i] = is64 ? lengths_raw[2 * i] : lengths_raw[i];
    }
    __syncthreads();

    for (;;) {
        if (tx == 0) s_chunk = (int)atomicAdd(&g_ticket, 1u);
        __syncthreads();
        const int c = s_chunk;
        __syncthreads();            // s_chunk read by all before next overwrite
        if (c >= numChunks) break;

        const int n0 = c * CHUNK_ROWS;

        // resolve source float4-offsets for the 4 rows (uniform work)
        int srcOff[CHUNK_ROWS];
        bool valid[CHUNK_ROWS];
        #pragma unroll
        for (int r = 0; r < CHUNK_ROWS; ++r) {
            const int n = n0 + r;
            valid[r] = (n < N);
            int s = 0, b = 0, t = 0;
            #pragma unroll 8
            for (int i = 0; i < B; ++i) {
                const int len = s_len[i];
                if (n >= s && n < s + len) { b = i; t = n - s; }
                s += len;
            }
            srcOff[r] = (b * Lmax + t) * ROW_VEC4;
        }

        // phase 1: 8 independent streaming loads (front-batched)
        float4 v[CHUNK_ROWS * VEC_PER_THREAD];
        #pragma unroll
        for (int r = 0; r < CHUNK_ROWS; ++r)
            #pragma unroll
            for (int j = 0; j < VEC_PER_THREAD; ++j)
                if (valid[r])
                    v[r * VEC_PER_THREAD + j] =
                        __ldcs(&in[srcOff[r] + tx + j * THREADS]);

        // phase 2: 8 streaming stores
        #pragma unroll
        for (int r = 0; r < CHUNK_ROWS; ++r) {
            float4* dst = out + (size_t)(n0 + r) * ROW_VEC4;
            #pragma unroll
            for (int j = 0; j < VEC_PER_THREAD; ++j)
                if (valid[r])
                    __stcs(&dst[tx + j * THREADS], v[r * VEC_PER_THREAD + j]);
        }
    }
}

extern "C" void kernel_launch(void* const* d_in, const int* in_sizes, int n_in,
                              void* d_out, int out_size)
{
    const float4* packed = (const float4*)d_in[0];   // [B, Lmax, H, D] fp32
    const int* lengths_raw = (const int*)d_in[1];    // [B] (int32 or int64 words)

    int B = in_sizes[1];
    if (B > MAX_B) B = MAX_B;
    long long total_in = in_sizes[0];                     // B*Lmax*2048 floats
    int Lmax = (int)(total_in / ((long long)B * 2048));   // 4096

    int N = out_size / 2048;                              // packed rows
    int numChunks = (N + CHUNK_ROWS - 1) / CHUNK_ROWS;

    float4* out = (float4*)d_out;

    reset_ticket_kernel<<<1, 1>>>();

    int grid = 6 * 148;                      // ~max resident blocks; stealing
    if (numChunks > 0 && grid > numChunks) grid = numChunks;
    if (grid < 1) grid = 1;

    unpack_ws_kernel<<<grid, THREADS>>>(
        packed, lengths_raw, out, B, Lmax, N, numChunks);
}

// round 11
// speedup vs baseline: 1.1072x; 1.0390x over previous
#include <cuda_runtime.h>
#include <stdint.h>

// Unpack padded [B, Lmax, H, D] fp32 -> packed [N, H, D], N = sum(lengths).
// Row = H*D = 2048 floats = 512 float4 = 8 KB.
//
// v6 (final form): R7's two-phase register copy — 4 rows/block, 8 front-
// batched LDG.128 + 8 STG.128 per thread, streaming (.cs) both ways — with a
// branch-free fast path for full blocks (only the last block predicates).
// Single launch, static grid. Measured: two different schedulers (static
// and work-stealing) both pin at 37.6 us = 256 MB bidir / 6.8 TB/s = ~85% of
// the 8 TB/s HBM spec, i.e. the mixed read/write turnaround ceiling.
//
// lengths dtype detected on-device (JAX x64-off downcasts int64 -> int32):
// parse as contiguous int32 AND int64-low-words; whichever sums to N wins.

#define ROW_VEC4        512          // float4 per row
#define THREADS         256
#define VEC_PER_THREAD  2            // 512 / 256
#define ROWS_PER_BLOCK  4
#define MAX_B           32

__global__ void __launch_bounds__(THREADS, 6) unpack_rows_final_kernel(
    const float4* __restrict__ in,        // [B, Lmax, 512]
    const int* __restrict__ lengths_raw,  // [B] raw words
    float4* __restrict__ out,             // [N, 512]
    int B, int Lmax, int N)
{
    const int n0 = blockIdx.x * ROWS_PER_BLOCK;
    const int tx = threadIdx.x;

    // --- dtype detection (B tiny; L1-resident, uniform across threads) ---
    long long sum32 = 0, sum64 = 0;
    #pragma unroll 8
    for (int i = 0; i < B; ++i) {
        sum32 += __ldg(&lengths_raw[i]);
        sum64 += __ldg(&lengths_raw[2 * i]);
    }
    const bool is64 = (sum64 == (long long)N) && (sum32 != (long long)N);

    // --- resolve source offsets (float4 units; < 2^24 so int is safe) ---
    int srcOff[ROWS_PER_BLOCK];
    #pragma unroll
    for (int r = 0; r < ROWS_PER_BLOCK; ++r) {
        const int n = n0 + r;
        int s = 0, b = 0, t = 0;
        #pragma unroll 8
        for (int i = 0; i < B; ++i) {
            const int len = is64 ? __ldg(&lengths_raw[2 * i]) : __ldg(&lengths_raw[i]);
            if (n >= s && n < s + len) { b = i; t = n - s; }
            s += len;
        }
        srcOff[r] = (b * Lmax + t) * ROW_VEC4;
    }

    if (n0 + ROWS_PER_BLOCK <= N) {
        // ---- fast path: branch-free 8 loads then 8 stores ----
        float4 v[ROWS_PER_BLOCK * VEC_PER_THREAD];
        #pragma unroll
        for (int r = 0; r < ROWS_PER_BLOCK; ++r)
            #pragma unroll
            for (int j = 0; j < VEC_PER_THREAD; ++j)
                v[r * VEC_PER_THREAD + j] =
                    __ldcs(&in[srcOff[r] + tx + j * THREADS]);

        #pragma unroll
        for (int r = 0; r < ROWS_PER_BLOCK; ++r) {
            float4* dst = out + (size_t)(n0 + r) * ROW_VEC4;
            #pragma unroll
            for (int j = 0; j < VEC_PER_THREAD; ++j)
                __stcs(&dst[tx + j * THREADS], v[r * VEC_PER_THREAD + j]);
        }
    } else {
        // ---- tail block (at most one per launch) ----
        for (int r = 0; r < ROWS_PER_BLOCK; ++r) {
            const int n = n0 + r;
            if (n >= N) break;
            float4* dst = out + (size_t)n * ROW_VEC4;
            #pragma unroll
            for (int j = 0; j < VEC_PER_THREAD; ++j)
                __stcs(&dst[tx + j * THREADS],
                       __ldcs(&in[srcOff[r] + tx + j * THREADS]));
        }
    }
}

extern "C" void kernel_launch(void* const* d_in, const int* in_sizes, int n_in,
                              void* d_out, int out_size)
{
    const float4* packed = (const float4*)d_in[0];   // [B, Lmax, H, D] fp32
    const int* lengths_raw = (const int*)d_in[1];    // [B] (int32 or int64 words)

    int B = in_sizes[1];
    if (B > MAX_B) B = MAX_B;
    long long total_in = in_sizes[0];                     // B*Lmax*2048 floats
    int Lmax = (int)(total_in / ((long long)B * 2048));   // 4096

    int N = out_size / 2048;                              // packed rows

    float4* out = (float4*)d_out;

    int grid = (N + ROWS_PER_BLOCK - 1) / ROWS_PER_BLOCK;
    if (grid < 1) grid = 1;
    unpack_rows_final_kernel<<<grid, THREADS>>>(packed, lengths_raw, out,
                                                B, Lmax, N);
}

// round 12
// speedup vs baseline: 1.1404x; 1.0300x over previous
#include <cuda_runtime.h>
#include <stdint.h>

// Unpack padded [B, Lmax, H, D] fp32 -> packed [N, H, D], N = sum(lengths).
// Row = H*D = 2048 floats = 512 float4 = 8 KB.
//
// FINAL (= R7, best measured): 4 rows per block, two-phase copy. Each thread
// front-batches 8 independent LDG.128 (MLP_p1=8), then issues 8 STG.128.
// Streaming cache hints (.cs) since every byte is touched exactly once.
//
// Measured roofline evidence: this kernel and a work-stealing variant of the
// same copy loop both pin at 37.6 us = 256 MB bidir / 6.8 TB/s = ~85% of the
// 8 TB/s HBM spec — the mixed read/write turnaround ceiling. MLP 16 (lower
// occ), cp.async smem pipelines, and branch-free restructures all measured
// equal or worse.
//
// lengths dtype detected on-device (JAX x64-off downcasts int64 -> int32):
// parse as contiguous int32 AND int64-low-words; whichever sums to N wins.

#define ROW_VEC4        512          // float4 per row
#define THREADS         256
#define VEC_PER_THREAD  (ROW_VEC4 / THREADS)   // 2
#define ROWS_PER_BLOCK  4
#define MAX_B           32

__global__ void __launch_bounds__(THREADS) unpack_rows4_kernel(
    const float4* __restrict__ in,        // [B, Lmax, 512] as float4
    const int* __restrict__ lengths_raw,  // [B] raw words
    float4* __restrict__ out,             // [N, 512] as float4
    int B, int Lmax, int N)
{
    const int n0 = blockIdx.x * ROWS_PER_BLOCK;

    // --- dtype detection (B tiny; L1-resident, uniform across threads) ---
    long long sum32 = 0, sum64 = 0;
    #pragma unroll 8
    for (int i = 0; i < B; ++i) {
        sum32 += __ldg(&lengths_raw[i]);
        sum64 += __ldg(&lengths_raw[2 * i]);
    }
    const bool is64 = (sum64 == (long long)N) && (sum32 != (long long)N);

    // --- resolve (b, t) for each of the 4 rows this block owns ---
    const float4* src[ROWS_PER_BLOCK];
    bool valid[ROWS_PER_BLOCK];
    #pragma unroll
    for (int r = 0; r < ROWS_PER_BLOCK; ++r) {
        const int n = n0 + r;
        valid[r] = (n < N);
        int s = 0, b = 0, t = 0;
        #pragma unroll 8
        for (int i = 0; i < B; ++i) {
            const int len = is64 ? __ldg(&lengths_raw[2 * i]) : __ldg(&lengths_raw[i]);
            if (n >= s && n < s + len) { b = i; t = n - s; }
            s += len;
        }
        src[r] = in + ((size_t)b * Lmax + (size_t)t) * ROW_VEC4;
    }

    // --- phase 1: 8 independent streaming loads (front-batched) ---
    float4 v[ROWS_PER_BLOCK * VEC_PER_THREAD];
    #pragma unroll
    for (int r = 0; r < ROWS_PER_BLOCK; ++r) {
        #pragma unroll
        for (int j = 0; j < VEC_PER_THREAD; ++j) {
            if (valid[r])
                v[r * VEC_PER_THREAD + j] =
                    __ldcs(&src[r][threadIdx.x + j * THREADS]);
        }
    }

    // --- phase 2: 8 streaming stores ---
    #pragma unroll
    for (int r = 0; r < ROWS_PER_BLOCK; ++r) {
        float4* dst = out + (size_t)(n0 + r) * ROW_VEC4;
        #pragma unroll
        for (int j = 0; j < VEC_PER_THREAD; ++j) {
            if (valid[r])
                __stcs(&dst[threadIdx.x + j * THREADS],
                       v[r * VEC_PER_THREAD + j]);
        }
    }
}

extern "C" void kernel_launch(void* const* d_in, const int* in_sizes, int n_in,
                              void* d_out, int out_size)
{
    const float4* packed = (const float4*)d_in[0];   // [B, Lmax, H, D] fp32
    const int* lengths_raw = (const int*)d_in[1];    // [B] (int32 or int64 words)

    int B = in_sizes[1];
    if (B > MAX_B) B = MAX_B;
    long long total_in = in_sizes[0];                     // B*Lmax*2048 floats
    int Lmax = (int)(total_in / ((long long)B * 2048));   // 4096

    int N = out_size / 2048;                              // packed rows

    float4* out = (float4*)d_out;

    int grid = (N + ROWS_PER_BLOCK - 1) / ROWS_PER_BLOCK;
    if (grid < 1) grid = 1;
    unpack_rows4_kernel<<<grid, THREADS>>>(packed, lengths_raw, out, B, Lmax, N);
}